// round 2
// baseline (speedup 1.0000x reference)
#include <cuda_runtime.h>
#include <math.h>

// ---------------- constants ----------------
#define NB   8
#define NRr  300
#define DD_  256         // model dim D
#define HH   8           // heads
#define HDIM 32          // head dim
#define SS   49
#define DCH  64          // DD (dynamic conv channels)
#define FFN  2048
#define NCL  80
#define ROWS (NB*NRr)    // 2400

// ---------------- scratch (device globals; no allocation allowed) ----------------
__device__ float g_qk   [ROWS*DD_];
__device__ float g_qp   [ROWS*DD_];
__device__ float g_kp   [ROWS*DD_];
__device__ float g_vp   [ROWS*DD_];
__device__ float g_mask [NB*NRr*NRr];
__device__ float g_ctx  [ROWS*DD_];
__device__ float g_tgt2 [ROWS*DD_];
__device__ float g_pf1  [ROWS*DD_];
__device__ float g_params[78643200];   // 2400*32768
__device__ float g_f2   [30105600];    // 2400*12544
__device__ float g_x    [ROWS*DD_];
__device__ float g_pf3  [ROWS*DD_];
__device__ float g_ffn  [ROWS*FFN];
__device__ float g_t2   [ROWS*DD_];
__device__ float g_fc   [ROWS*DD_];
__device__ float g_clsy [ROWS*DD_];
__device__ float g_clsf [ROWS*DD_];

// ---------------- helpers ----------------
__device__ __forceinline__ float blockReduceSum256(float v) {
    __shared__ float red[8];
    int lane = threadIdx.x & 31, w = threadIdx.x >> 5;
    #pragma unroll
    for (int o = 16; o; o >>= 1) v += __shfl_xor_sync(0xffffffffu, v, o);
    __syncthreads();
    if (lane == 0) red[w] = v;
    __syncthreads();
    float s = 0.f;
    #pragma unroll
    for (int i = 0; i < 8; i++) s += red[i];
    return s;
}

// ---------------- IoU-relation attention mask ----------------
__global__ void mask_kernel(const float* __restrict__ bboxes,
                            const float* __restrict__ cur,
                            float* __restrict__ maskf) {
    int q = blockIdx.x, b = blockIdx.y, k = threadIdx.x;
    if (k >= NRr) return;
    float4 bq = *(const float4*)(bboxes + (size_t)(b*NRr + q)*4);
    float4 bk = *(const float4*)(bboxes + (size_t)(b*NRr + k)*4);
    float aq = (bq.z-bq.x)*(bq.w-bq.y);
    float ak = (bk.z-bk.x)*(bk.w-bk.y);
    float lx = fmaxf(bq.x, bk.x), ly = fmaxf(bq.y, bk.y);
    float rx = fminf(bq.z, bk.z), ry = fminf(bq.w, bk.w);
    float w  = fmaxf(rx-lx, 0.f), h = fmaxf(ry-ly, 0.f);
    float inter = w*h;
    float uni = fmaxf(aq + ak - inter, 1e-9f);
    float iou = inter/uni;
    float o   = (iou < 0.5f) ? 1.f : 0.f;
    float cq = cur[b*NRr + q], ck = cur[b*NRr + k];
    float val = o*cq*ck + ((q == k) ? (1.f - cq) : 0.f);
    maskf[((size_t)(b*NRr + q))*NRr + k] = (val > 0.f) ? 1.f : 0.f;
}

// ---------------- elementwise add (qk = pf + query) ----------------
__global__ void add_kernel(const float* __restrict__ a, const float* __restrict__ b,
                           float* __restrict__ c, int n) {
    int i = blockIdx.x*blockDim.x + threadIdx.x;
    if (i < n) c[i] = a[i] + b[i];
}

// ---------------- generic tiled SGEMM: C[M,N] = A[M,K] @ B[N,K]^T + bias, opt relu ----------------
// K must be a multiple of 16 (true for 256 / 2048 / 12544).
__global__ void sgemm_bias(const float* __restrict__ A, const float* __restrict__ B,
                           const float* __restrict__ bias, float* __restrict__ C,
                           int M, int N, int K, int doRelu) {
    __shared__ float As[16][64];
    __shared__ float Bs[16][64];
    const int tid = threadIdx.x;              // 256
    const int row0 = blockIdx.y * 64;
    const int col0 = blockIdx.x * 64;
    const int lr  = tid >> 2;                 // 0..63
    const int lc4 = (tid & 3) * 4;            // 0,4,8,12
    const int tr = (tid >> 4) * 4;            // 0..60
    const int tc = (tid & 15) * 4;
    float acc[4][4];
    #pragma unroll
    for (int i = 0; i < 4; i++)
        #pragma unroll
        for (int j = 0; j < 4; j++) acc[i][j] = 0.f;

    for (int k0 = 0; k0 < K; k0 += 16) {
        float4 av = make_float4(0.f,0.f,0.f,0.f);
        if (row0 + lr < M) av = *(const float4*)(A + (size_t)(row0+lr)*K + k0 + lc4);
        As[lc4+0][lr] = av.x; As[lc4+1][lr] = av.y; As[lc4+2][lr] = av.z; As[lc4+3][lr] = av.w;
        float4 bv = make_float4(0.f,0.f,0.f,0.f);
        if (col0 + lr < N) bv = *(const float4*)(B + (size_t)(col0+lr)*K + k0 + lc4);
        Bs[lc4+0][lr] = bv.x; Bs[lc4+1][lr] = bv.y; Bs[lc4+2][lr] = bv.z; Bs[lc4+3][lr] = bv.w;
        __syncthreads();
        #pragma unroll
        for (int kk = 0; kk < 16; kk++) {
            float a[4], b[4];
            #pragma unroll
            for (int i = 0; i < 4; i++) a[i] = As[kk][tr+i];
            #pragma unroll
            for (int j = 0; j < 4; j++) b[j] = Bs[kk][tc+j];
            #pragma unroll
            for (int i = 0; i < 4; i++)
                #pragma unroll
                for (int j = 0; j < 4; j++) acc[i][j] += a[i]*b[j];
        }
        __syncthreads();
    }
    #pragma unroll
    for (int i = 0; i < 4; i++) {
        int r = row0 + tr + i;
        if (r >= M) continue;
        #pragma unroll
        for (int j = 0; j < 4; j++) {
            int c = col0 + tc + j;
            if (c >= N) continue;
            float v = acc[i][j] + (bias ? bias[c] : 0.f);
            if (doRelu) v = fmaxf(v, 0.f);
            C[(size_t)r*N + c] = v;
        }
    }
}

// ---------------- masked multi-head attention (online softmax) ----------------
// one block per (b,h); K/V tiles streamed through SMEM in chunks of 150.
__global__ void attn_kernel(const float* __restrict__ qp, const float* __restrict__ kp,
                            const float* __restrict__ vp, const float* __restrict__ maskf,
                            float* __restrict__ ctx) {
    const int b = blockIdx.x >> 3;
    const int h = blockIdx.x & 7;
    __shared__ float Ks[150*32];
    __shared__ float Vs[150*32];
    const int tid = threadIdx.x;          // 320
    const int q = tid;
    float qv[32], acc[32];
    float m = -1e30f, ssum = 0.f;
    if (q < NRr) {
        const float* qr = qp + ((size_t)(b*NRr + q))*DD_ + h*HDIM;
        #pragma unroll
        for (int d = 0; d < 32; d++) { qv[d] = qr[d]; acc[d] = 0.f; }
    }
    const float* mrow = maskf + ((size_t)(b*NRr) + (q < NRr ? q : 0))*NRr;
    const float scale = 0.17677669529663687f;  // 1/sqrt(32)

    for (int c0 = 0; c0 < NRr; c0 += 150) {
        __syncthreads();
        for (int i = tid; i < 150*32; i += 320) {
            int k = i >> 5, d = i & 31;
            size_t gi = ((size_t)(b*NRr + c0 + k))*DD_ + h*HDIM + d;
            Ks[i] = kp[gi];
            Vs[i] = vp[gi];
        }
        __syncthreads();
        if (q < NRr) {
            for (int k = 0; k < 150; k++) {
                const float* kr = Ks + k*32;
                float x = 0.f;
                #pragma unroll
                for (int d = 0; d < 32; d++) x += qv[d]*kr[d];
                x *= scale;
                if (mrow[c0+k] > 0.f) x = -1e9f;
                float nm = fmaxf(m, x);
                float sc = __expf(m - nm);
                float e  = __expf(x - nm);
                ssum = ssum*sc + e;
                const float* vr = Vs + k*32;
                #pragma unroll
                for (int d = 0; d < 32; d++) acc[d] = acc[d]*sc + e*vr[d];
                m = nm;
            }
        }
    }
    if (q < NRr) {
        float inv = 1.f/ssum;
        float* cr = ctx + ((size_t)(b*NRr + q))*DD_ + h*HDIM;
        #pragma unroll
        for (int d = 0; d < 32; d++) cr[d] = acc[d]*inv;
    }
}

// ---------------- ln(residual) * mask (used for norm1 and norm3+cls-mask) ----------------
__global__ void ln_res_mask_kernel(const float* __restrict__ a, const float* __restrict__ bq,
                                   const float* __restrict__ cur, float* __restrict__ out) {
    int r = blockIdx.x, t = threadIdx.x;
    float x = a[(size_t)r*DD_ + t] + bq[(size_t)r*DD_ + t];
    float mean = blockReduceSum256(x) * (1.f/256.f);
    float d = x - mean;
    float var = blockReduceSum256(d*d) * (1.f/256.f);
    out[(size_t)r*DD_ + t] = d * rsqrtf(var + 1e-5f) * cur[r];
}

// ---------------- relu(ln(x)) -> + pf1 -> ln  (norm2 path) ----------------
__global__ void post_dyn_kernel(const float* __restrict__ x, const float* __restrict__ pf1,
                                float* __restrict__ out) {
    int r = blockIdx.x, t = threadIdx.x;
    float v = x[(size_t)r*DD_ + t];
    float m1 = blockReduceSum256(v) * (1.f/256.f);
    float d1 = v - m1;
    float v1 = blockReduceSum256(d1*d1) * (1.f/256.f);
    float rl = fmaxf(d1 * rsqrtf(v1 + 1e-5f), 0.f);
    float y = pf1[(size_t)r*DD_ + t] + rl;
    float m2 = blockReduceSum256(y) * (1.f/256.f);
    float d2 = y - m2;
    float v2 = blockReduceSum256(d2*d2) * (1.f/256.f);
    out[(size_t)r*DD_ + t] = d2 * rsqrtf(v2 + 1e-5f);
}

// ---------------- relu(ln(x)) ----------------
__global__ void ln_relu_kernel(const float* __restrict__ x, float* __restrict__ out) {
    int r = blockIdx.x, t = threadIdx.x;
    float v = x[(size_t)r*DD_ + t];
    float m = blockReduceSum256(v) * (1.f/256.f);
    float d = v - m;
    float var = blockReduceSum256(d*d) * (1.f/256.f);
    out[(size_t)r*DD_ + t] = fmaxf(d * rsqrtf(var + 1e-5f), 0.f);
}

// ---------------- DynamicConv: one block per instance ----------------
// smem: feats[49][256] | p1[256][64] | p2[64][256] | f1[49][64]  = 193792 B
__global__ void dynconv_kernel(const float* __restrict__ roi, const float* __restrict__ params,
                               float* __restrict__ out) {
    int n = blockIdx.x;
    extern __shared__ float sm[];
    float* feats = sm;              // 12544
    float* p1    = sm + 12544;      // 16384
    float* p2    = p1 + 16384;      // 16384
    float* f1    = p2 + 16384;      // 3136
    int tid = threadIdx.x;          // 256
    // load feats[s][d] = roi[s, n, d]
    for (int i = tid; i < SS*DD_; i += 256) {
        int s = i >> 8, d = i & 255;
        feats[i] = roi[((size_t)s*ROWS + n)*DD_ + d];
    }
    const float* pr = params + (size_t)n * 32768;
    for (int i = tid; i < 16384; i += 256) p1[i] = pr[i];
    for (int i = tid; i < 16384; i += 256) p2[i] = pr[16384 + i];
    __syncthreads();
    // f1[s][e] = sum_d feats[s][d]*p1[d][e]
    for (int o = tid; o < SS*DCH; o += 256) {
        int s = o >> 6, e = o & 63;
        float acc = 0.f;
        const float* fr = feats + s*DD_;
        #pragma unroll 4
        for (int d = 0; d < 256; d++) acc += fr[d] * p1[d*64 + e];
        f1[o] = acc;
    }
    __syncthreads();
    int warp = tid >> 5, lane = tid & 31;
    // LN over 64 + relu, per s row
    for (int s = warp; s < SS; s += 8) {
        float x0 = f1[s*64 + lane], x1 = f1[s*64 + 32 + lane];
        float sum = x0 + x1;
        #pragma unroll
        for (int o = 16; o; o >>= 1) sum += __shfl_xor_sync(0xffffffffu, sum, o);
        float m = sum * (1.f/64.f);
        float d0 = x0 - m, d1 = x1 - m;
        float vs = d0*d0 + d1*d1;
        #pragma unroll
        for (int o = 16; o; o >>= 1) vs += __shfl_xor_sync(0xffffffffu, vs, o);
        float inv = rsqrtf(vs*(1.f/64.f) + 1e-5f);
        f1[s*64 + lane]      = fmaxf(d0*inv, 0.f);
        f1[s*64 + 32 + lane] = fmaxf(d1*inv, 0.f);
    }
    __syncthreads();
    // f2[s][d] = sum_e f1[s][e]*p2[e][d]  (overwrites feats region)
    float* f2 = feats;
    for (int o = tid; o < SS*DD_; o += 256) {
        int s = o >> 8, d = o & 255;
        float acc = 0.f;
        const float* f1r = f1 + s*64;
        #pragma unroll 8
        for (int e = 0; e < 64; e++) acc += f1r[e] * p2[e*256 + d];
        f2[o] = acc;
    }
    __syncthreads();
    // LN over 256 + relu, write out
    for (int s = warp; s < SS; s += 8) {
        float x[8]; float sum = 0.f;
        #pragma unroll
        for (int j = 0; j < 8; j++) { x[j] = f2[s*256 + j*32 + lane]; sum += x[j]; }
        #pragma unroll
        for (int o = 16; o; o >>= 1) sum += __shfl_xor_sync(0xffffffffu, sum, o);
        float m = sum * (1.f/256.f);
        float vs = 0.f;
        #pragma unroll
        for (int j = 0; j < 8; j++) { float dd = x[j]-m; vs += dd*dd; }
        #pragma unroll
        for (int o = 16; o; o >>= 1) vs += __shfl_xor_sync(0xffffffffu, vs, o);
        float inv = rsqrtf(vs*(1.f/256.f) + 1e-5f);
        #pragma unroll
        for (int j = 0; j < 8; j++)
            out[(size_t)n*12544 + s*256 + j*32 + lane] = fmaxf((x[j]-m)*inv, 0.f);
    }
}

// ---------------- host ----------------
extern "C" void kernel_launch(void* const* d_in, const int* in_sizes, int n_in,
                              void* d_out, int out_size) {
    const float* bboxes     = (const float*)d_in[0];
    const float* pf         = (const float*)d_in[1];
    const float* roi        = (const float*)d_in[2];
    const float* query      = (const float*)d_in[3];
    const float* cur        = (const float*)d_in[4];
    const float* w_qkv      = (const float*)d_in[5];
    const float* b_qkv      = (const float*)d_in[6];
    const float* w_attn_out = (const float*)d_in[7];
    const float* b_attn_out = (const float*)d_in[8];
    const float* w_dyn      = (const float*)d_in[9];
    const float* b_dyn      = (const float*)d_in[10];
    const float* w_dyn_out  = (const float*)d_in[11];
    const float* b_dyn_out  = (const float*)d_in[12];
    const float* w_ff1      = (const float*)d_in[13];
    const float* b_ff1      = (const float*)d_in[14];
    const float* w_ff2      = (const float*)d_in[15];
    const float* b_ff2      = (const float*)d_in[16];
    const float* w_cls      = (const float*)d_in[17];
    const float* w_logits   = (const float*)d_in[18];
    const float* b_logits   = (const float*)d_in[19];
    float* out = (float*)d_out;

    float *qk,*qp,*kp,*vp,*maskb,*ctx,*tgt2,*pf1,*params,*f2,*x,*pf3,*ffn,*t2,*fc,*clsy,*clsf;
    cudaGetSymbolAddress((void**)&qk,    g_qk);
    cudaGetSymbolAddress((void**)&qp,    g_qp);
    cudaGetSymbolAddress((void**)&kp,    g_kp);
    cudaGetSymbolAddress((void**)&vp,    g_vp);
    cudaGetSymbolAddress((void**)&maskb, g_mask);
    cudaGetSymbolAddress((void**)&ctx,   g_ctx);
    cudaGetSymbolAddress((void**)&tgt2,  g_tgt2);
    cudaGetSymbolAddress((void**)&pf1,   g_pf1);
    cudaGetSymbolAddress((void**)&params,g_params);
    cudaGetSymbolAddress((void**)&f2,    g_f2);
    cudaGetSymbolAddress((void**)&x,     g_x);
    cudaGetSymbolAddress((void**)&pf3,   g_pf3);
    cudaGetSymbolAddress((void**)&ffn,   g_ffn);
    cudaGetSymbolAddress((void**)&t2,    g_t2);
    cudaGetSymbolAddress((void**)&fc,    g_fc);
    cudaGetSymbolAddress((void**)&clsy,  g_clsy);
    cudaGetSymbolAddress((void**)&clsf,  g_clsf);

    cudaFuncSetAttribute(dynconv_kernel, cudaFuncAttributeMaxDynamicSharedMemorySize, 193792);

    auto grd = [](int M, int N) { return dim3((unsigned)((N+63)/64), (unsigned)((M+63)/64)); };

    // 1. IoU-relation mask
    mask_kernel<<<dim3(NRr, NB), 320>>>(bboxes, cur, maskb);
    // 2. qk = pf + query
    add_kernel<<<(ROWS*DD_+255)/256, 256>>>(pf, query, qk, ROWS*DD_);
    // 3. QKV projections
    sgemm_bias<<<grd(ROWS,256), 256>>>(qk, w_qkv,           b_qkv,     qp, ROWS, 256, 256, 0);
    sgemm_bias<<<grd(ROWS,256), 256>>>(qk, w_qkv + 256*256, b_qkv+256, kp, ROWS, 256, 256, 0);
    sgemm_bias<<<grd(ROWS,256), 256>>>(pf, w_qkv + 512*256, b_qkv+512, vp, ROWS, 256, 256, 0);
    // 4. masked MHSA
    attn_kernel<<<NB*HH, 320>>>(qp, kp, vp, maskb, ctx);
    // 5. out proj + norm1*mask
    sgemm_bias<<<grd(ROWS,256), 256>>>(ctx, w_attn_out, b_attn_out, tgt2, ROWS, 256, 256, 0);
    ln_res_mask_kernel<<<ROWS, 256>>>(pf, tgt2, cur, pf1);
    // 6. DynamicConv params GEMM (dominant)
    sgemm_bias<<<grd(ROWS,32768), 256>>>(pf1, w_dyn, b_dyn, params, ROWS, 32768, 256, 0);
    // 7. per-instance dynamic conv
    dynconv_kernel<<<ROWS, 256, 193792>>>(roi, params, f2);
    // 8. dyn out proj + norm2
    sgemm_bias<<<grd(ROWS,256), 256>>>(f2, w_dyn_out, b_dyn_out, x, ROWS, 256, 12544, 0);
    post_dyn_kernel<<<ROWS, 256>>>(x, pf1, pf3);
    // 9. FFN + norm3 (with cls mask fused)
    sgemm_bias<<<grd(ROWS,2048), 256>>>(pf3, w_ff1, b_ff1, ffn, ROWS, 2048, 256, 1);
    sgemm_bias<<<grd(ROWS,256),  256>>>(ffn, w_ff2, b_ff2, t2, ROWS, 256, 2048, 0);
    ln_res_mask_kernel<<<ROWS, 256>>>(pf3, t2, cur, fc);
    // 10. cls tower + logits
    sgemm_bias<<<grd(ROWS,256), 256>>>(fc, w_cls, nullptr, clsy, ROWS, 256, 256, 0);
    ln_relu_kernel<<<ROWS, 256>>>(clsy, clsf);
    sgemm_bias<<<grd(ROWS,80), 256>>>(clsf, w_logits, b_logits, out, ROWS, 80, 256, 0);
}

// round 4
// speedup vs baseline: 2.1642x; 2.1642x over previous
#include <cuda_runtime.h>
#include <math.h>
#include <stdint.h>

// ---------------- constants ----------------
#define NB   8
#define NRr  300
#define DD_  256
#define HH   8
#define HDIM 32
#define SS   49
#define DCH  64
#define FFN  2048
#define NCL  80
#define ROWS (NB*NRr)    // 2400

// ---------------- scratch ----------------
__device__ float g_qk   [ROWS*DD_];
__device__ float g_qp   [ROWS*DD_];
__device__ float g_kp   [ROWS*DD_];
__device__ float g_vp   [ROWS*DD_];
__device__ float g_mask [NB*NRr*NRr];
__device__ float g_ctx  [ROWS*DD_];
__device__ float g_tgt2 [ROWS*DD_];
__device__ float g_pf1  [ROWS*DD_];
__device__ float g_params[78643200];   // 2400*32768
__device__ float g_f2   [30105600];    // 2400*12544
__device__ float g_x    [ROWS*DD_];
__device__ float g_pf3  [ROWS*DD_];
__device__ float g_ffn  [ROWS*FFN];
__device__ float g_t2   [ROWS*DD_];
__device__ float g_fc   [ROWS*DD_];
__device__ float g_clsy [ROWS*DD_];
__device__ float g_clsf [ROWS*DD_];

// ---------------- helpers ----------------
__device__ __forceinline__ float blockReduceSum256(float v) {
    __shared__ float red[8];
    int lane = threadIdx.x & 31, w = threadIdx.x >> 5;
    #pragma unroll
    for (int o = 16; o; o >>= 1) v += __shfl_xor_sync(0xffffffffu, v, o);
    __syncthreads();
    if (lane == 0) red[w] = v;
    __syncthreads();
    float s = 0.f;
    #pragma unroll
    for (int i = 0; i < 8; i++) s += red[i];
    return s;
}

__device__ __forceinline__ uint32_t f2tf(float x) {
    uint32_t u;
    asm("cvt.rna.tf32.f32 %0, %1;" : "=r"(u) : "f"(x));
    return u;
}

__device__ __forceinline__ void mma_tf32(float* c,
        uint32_t a0, uint32_t a1, uint32_t a2, uint32_t a3,
        uint32_t b0, uint32_t b1) {
    asm volatile(
        "mma.sync.aligned.m16n8k8.row.col.f32.tf32.tf32.f32 "
        "{%0,%1,%2,%3}, {%4,%5,%6,%7}, {%8,%9}, {%0,%1,%2,%3};"
        : "+f"(c[0]), "+f"(c[1]), "+f"(c[2]), "+f"(c[3])
        : "r"(a0), "r"(a1), "r"(a2), "r"(a3), "r"(b0), "r"(b1));
}

// ---------------- TF32 tensor-core GEMM: C[M,N] = A[M,K] @ B[N,K]^T + bias ----------------
// BM=128 BN=128 BK=32, 256 threads (8 warps: 4x2), double-buffered cp.async.
// K must be a multiple of 32 and >= 64.
#define GTILE 4608   // 128*36 floats per buffer

__device__ __forceinline__ void gemm_load_tile(
        const float* __restrict__ A, const float* __restrict__ B,
        int M, int N, int K, int row0, int col0,
        uint32_t sbase, int tid, int buf, int k0) {
    int r  = tid >> 3;
    int c4 = (tid & 7) * 4;
    #pragma unroll
    for (int p = 0; p < 4; p++) {
        int rr = r + p * 32;
        int gr = row0 + rr;
        const float* src = A + (size_t)(gr < M ? gr : (M - 1)) * K + k0 + c4;
        uint32_t dst = sbase + (uint32_t)((buf * GTILE + rr * 36 + c4) * 4);
        int sz = (gr < M) ? 16 : 0;
        asm volatile("cp.async.cg.shared.global [%0], [%1], 16, %2;\n"
                     :: "r"(dst), "l"(src), "r"(sz));
    }
    #pragma unroll
    for (int p = 0; p < 4; p++) {
        int rr = r + p * 32;
        int gn = col0 + rr;
        const float* src = B + (size_t)(gn < N ? gn : (N - 1)) * K + k0 + c4;
        uint32_t dst = sbase + (uint32_t)(((2 * GTILE) + buf * GTILE + rr * 36 + c4) * 4);
        int sz = (gn < N) ? 16 : 0;
        asm volatile("cp.async.cg.shared.global [%0], [%1], 16, %2;\n"
                     :: "r"(dst), "l"(src), "r"(sz));
    }
}

__global__ __launch_bounds__(256)
void tf32_gemm(const float* __restrict__ A, const float* __restrict__ B,
               const float* __restrict__ bias, float* __restrict__ C,
               int M, int N, int K, int doRelu) {
    extern __shared__ float sm[];
    const int tid  = threadIdx.x;
    const int warp = tid >> 5, lane = tid & 31;
    const int wm = warp >> 1, wn = warp & 1;
    const int row0 = blockIdx.y * 128;
    const int col0 = blockIdx.x * 128;
    uint32_t sbase = (uint32_t)__cvta_generic_to_shared(sm);

    float acc[2][8][4];
    #pragma unroll
    for (int i = 0; i < 2; i++)
        #pragma unroll
        for (int j = 0; j < 8; j++)
            #pragma unroll
            for (int k = 0; k < 4; k++) acc[i][j][k] = 0.f;

    const int T = K >> 5;
    gemm_load_tile(A, B, M, N, K, row0, col0, sbase, tid, 0, 0);
    asm volatile("cp.async.commit_group;");

    for (int t = 0; t < T; t++) {
        if (t + 1 < T) {
            gemm_load_tile(A, B, M, N, K, row0, col0, sbase, tid, (t + 1) & 1, (t + 1) * 32);
            asm volatile("cp.async.commit_group;");
            asm volatile("cp.async.wait_group 1;");
        } else {
            asm volatile("cp.async.wait_group 0;");
        }
        __syncthreads();

        const float* as = sm + (t & 1) * GTILE;
        const float* bs = sm + 2 * GTILE + (t & 1) * GTILE;
        #pragma unroll
        for (int kk = 0; kk < 4; kk++) {
            const int kb = kk * 8 + (lane & 3);
            uint32_t a[2][4];
            #pragma unroll
            for (int mi = 0; mi < 2; mi++) {
                const float* ap = as + (wm * 32 + mi * 16 + (lane >> 2)) * 36 + kb;
                a[mi][0] = f2tf(ap[0]);
                a[mi][1] = f2tf(ap[8 * 36]);
                a[mi][2] = f2tf(ap[4]);
                a[mi][3] = f2tf(ap[8 * 36 + 4]);
            }
            #pragma unroll
            for (int ni = 0; ni < 8; ni++) {
                const float* bp = bs + (wn * 64 + ni * 8 + (lane >> 2)) * 36 + kb;
                uint32_t b0 = f2tf(bp[0]);
                uint32_t b1 = f2tf(bp[4]);
                #pragma unroll
                for (int mi = 0; mi < 2; mi++)
                    mma_tf32(acc[mi][ni], a[mi][0], a[mi][1], a[mi][2], a[mi][3], b0, b1);
            }
        }
        __syncthreads();
    }

    // epilogue
    #pragma unroll
    for (int mi = 0; mi < 2; mi++) {
        int gr0 = row0 + wm * 32 + mi * 16 + (lane >> 2);
        #pragma unroll
        for (int ni = 0; ni < 8; ni++) {
            int gc = col0 + wn * 64 + ni * 8 + 2 * (lane & 3);
            if (gc >= N) continue;
            float bb0 = 0.f, bb1 = 0.f;
            if (bias) { bb0 = bias[gc]; bb1 = bias[gc + 1]; }
            if (gr0 < M) {
                float v0 = acc[mi][ni][0] + bb0;
                float v1 = acc[mi][ni][1] + bb1;
                if (doRelu) { v0 = fmaxf(v0, 0.f); v1 = fmaxf(v1, 0.f); }
                float2 o = make_float2(v0, v1);
                *(float2*)(C + (size_t)gr0 * N + gc) = o;
            }
            if (gr0 + 8 < M) {
                float v0 = acc[mi][ni][2] + bb0;
                float v1 = acc[mi][ni][3] + bb1;
                if (doRelu) { v0 = fmaxf(v0, 0.f); v1 = fmaxf(v1, 0.f); }
                float2 o = make_float2(v0, v1);
                *(float2*)(C + (size_t)(gr0 + 8) * N + gc) = o;
            }
        }
    }
}

// ---------------- IoU-relation attention mask ----------------
__global__ void mask_kernel(const float* __restrict__ bboxes,
                            const float* __restrict__ cur,
                            float* __restrict__ maskf) {
    int q = blockIdx.x, b = blockIdx.y, k = threadIdx.x;
    if (k >= NRr) return;
    float4 bq = *(const float4*)(bboxes + (size_t)(b*NRr + q)*4);
    float4 bk = *(const float4*)(bboxes + (size_t)(b*NRr + k)*4);
    float aq = (bq.z-bq.x)*(bq.w-bq.y);
    float ak = (bk.z-bk.x)*(bk.w-bk.y);
    float lx = fmaxf(bq.x, bk.x), ly = fmaxf(bq.y, bk.y);
    float rx = fminf(bq.z, bk.z), ry = fminf(bq.w, bk.w);
    float w  = fmaxf(rx-lx, 0.f), h = fmaxf(ry-ly, 0.f);
    float inter = w*h;
    float uni = fmaxf(aq + ak - inter, 1e-9f);
    float iou = inter/uni;
    float o   = (iou < 0.5f) ? 1.f : 0.f;
    float cq = cur[b*NRr + q], ck = cur[b*NRr + k];
    float val = o*cq*ck + ((q == k) ? (1.f - cq) : 0.f);
    maskf[((size_t)(b*NRr + q))*NRr + k] = (val > 0.f) ? 1.f : 0.f;
}

// ---------------- elementwise add ----------------
__global__ void add_kernel(const float* __restrict__ a, const float* __restrict__ b,
                           float* __restrict__ c, int n) {
    int i = blockIdx.x*blockDim.x + threadIdx.x;
    if (i < n) c[i] = a[i] + b[i];
}

// ---------------- masked multi-head attention (online softmax, q-chunked) ----------------
#define QCH 100
__global__ void attn_kernel(const float* __restrict__ qp, const float* __restrict__ kp,
                            const float* __restrict__ vp, const float* __restrict__ maskf,
                            float* __restrict__ ctx) {
    const int bh = blockIdx.x / 3;
    const int ch = blockIdx.x % 3;
    const int b = bh >> 3;
    const int h = bh & 7;
    __shared__ float Ks[150*32];
    __shared__ float Vs[150*32];
    const int tid = threadIdx.x;          // 128
    const int q = ch * QCH + tid;
    const bool act = (tid < QCH) && (q < NRr);
    float qv[32], acc[32];
    float m = -1e30f, ssum = 0.f;
    if (act) {
        const float* qr = qp + ((size_t)(b*NRr + q))*DD_ + h*HDIM;
        #pragma unroll
        for (int d = 0; d < 32; d++) { qv[d] = qr[d]; acc[d] = 0.f; }
    }
    const float* mrow = maskf + ((size_t)(b*NRr) + (act ? q : 0))*NRr;
    const float scale = 0.17677669529663687f;  // 1/sqrt(32)

    for (int c0 = 0; c0 < NRr; c0 += 150) {
        __syncthreads();
        for (int i = tid; i < 150*32; i += 128) {
            int k = i >> 5, d = i & 31;
            size_t gi = ((size_t)(b*NRr + c0 + k))*DD_ + h*HDIM + d;
            Ks[i] = kp[gi];
            Vs[i] = vp[gi];
        }
        __syncthreads();
        if (act) {
            for (int k = 0; k < 150; k++) {
                const float* kr = Ks + k*32;
                float x0 = 0.f, x1 = 0.f, x2 = 0.f, x3 = 0.f;
                #pragma unroll
                for (int d = 0; d < 32; d += 4) {
                    x0 += qv[d]*kr[d];   x1 += qv[d+1]*kr[d+1];
                    x2 += qv[d+2]*kr[d+2]; x3 += qv[d+3]*kr[d+3];
                }
                float x = ((x0+x1)+(x2+x3))*scale;
                if (mrow[c0+k] > 0.f) x = -1e9f;
                float nm = fmaxf(m, x);
                float sc = __expf(m - nm);
                float e  = __expf(x - nm);
                ssum = ssum*sc + e;
                const float* vr = Vs + k*32;
                #pragma unroll
                for (int d = 0; d < 32; d++) acc[d] = acc[d]*sc + e*vr[d];
                m = nm;
            }
        }
    }
    if (act) {
        float inv = 1.f/ssum;
        float* cr = ctx + ((size_t)(b*NRr + q))*DD_ + h*HDIM;
        #pragma unroll
        for (int d = 0; d < 32; d++) cr[d] = acc[d]*inv;
    }
}

// ---------------- ln(residual) * mask ----------------
__global__ void ln_res_mask_kernel(const float* __restrict__ a, const float* __restrict__ bq,
                                   const float* __restrict__ cur, float* __restrict__ out) {
    int r = blockIdx.x, t = threadIdx.x;
    float x = a[(size_t)r*DD_ + t] + bq[(size_t)r*DD_ + t];
    float mean = blockReduceSum256(x) * (1.f/256.f);
    float d = x - mean;
    float var = blockReduceSum256(d*d) * (1.f/256.f);
    out[(size_t)r*DD_ + t] = d * rsqrtf(var + 1e-5f) * cur[r];
}

// ---------------- relu(ln(x)) -> + pf1 -> ln ----------------
__global__ void post_dyn_kernel(const float* __restrict__ x, const float* __restrict__ pf1,
                                float* __restrict__ out) {
    int r = blockIdx.x, t = threadIdx.x;
    float v = x[(size_t)r*DD_ + t];
    float m1 = blockReduceSum256(v) * (1.f/256.f);
    float d1 = v - m1;
    float v1 = blockReduceSum256(d1*d1) * (1.f/256.f);
    float rl = fmaxf(d1 * rsqrtf(v1 + 1e-5f), 0.f);
    float y = pf1[(size_t)r*DD_ + t] + rl;
    float m2 = blockReduceSum256(y) * (1.f/256.f);
    float d2 = y - m2;
    float v2 = blockReduceSum256(d2*d2) * (1.f/256.f);
    out[(size_t)r*DD_ + t] = d2 * rsqrtf(v2 + 1e-5f);
}

// ---------------- relu(ln(x)) ----------------
__global__ void ln_relu_kernel(const float* __restrict__ x, float* __restrict__ out) {
    int r = blockIdx.x, t = threadIdx.x;
    float v = x[(size_t)r*DD_ + t];
    float m = blockReduceSum256(v) * (1.f/256.f);
    float d = v - m;
    float var = blockReduceSum256(d*d) * (1.f/256.f);
    out[(size_t)r*DD_ + t] = fmaxf(d * rsqrtf(var + 1e-5f), 0.f);
}

// ---------------- DynamicConv (register-tiled, FMA-bound) ----------------
// smem floats: featsT[256*52] @0 (also reused as f2[52*256]) | p1[256*64] @13312
//              | p2[64*256] @29696 | f1[52*64] @46080 | f1T[64*52] @49408
// total 52736 floats = 210944 B
#define SPAD 52
#define DYN_SMEM 210944

__global__ __launch_bounds__(256)
void dynconv_kernel(const float* __restrict__ roi, const float* __restrict__ params,
                    float* __restrict__ out) {
    int n = blockIdx.x;
    extern __shared__ float sm[];
    float* featsT = sm;                 // [d][s] 256 x 52
    float* p1     = sm + 13312;         // [d][e] 256 x 64
    float* p2     = p1 + 16384;         // [e][d] 64 x 256
    float* f1     = p2 + 16384;         // [s][e] 52 x 64
    float* f1T    = f1 + 3328;          // [e][s] 64 x 52
    int tid = threadIdx.x;

    // zero pad rows s=49..51
    for (int i = tid; i < 256*3; i += 256) {
        int d = i / 3, s = 49 + (i % 3);
        featsT[d*SPAD + s] = 0.f;
    }
    // transpose-load feats
    for (int i = tid; i < SS*DD_; i += 256) {
        int s = i >> 8, d = i & 255;
        featsT[d*SPAD + s] = roi[((size_t)s*ROWS + n)*DD_ + d];
    }
    // load p1, p2
    const float4* pr = (const float4*)(params + (size_t)n * 32768);
    float4* p14 = (float4*)p1;
    float4* p24 = (float4*)p2;
    for (int i = tid; i < 4096; i += 256) p14[i] = pr[i];
    for (int i = tid; i < 4096; i += 256) p24[i] = pr[4096 + i];
    __syncthreads();

    // stage1: f1[s][e] = sum_d featsT[d][s] * p1[d][e]
    {
        int te = tid & 15, tsg = tid >> 4;
        if (tsg < 13) {
            int e0 = te * 4, s0 = tsg * 4;
            float acc[4][4];
            #pragma unroll
            for (int i = 0; i < 4; i++)
                #pragma unroll
                for (int j = 0; j < 4; j++) acc[i][j] = 0.f;
            for (int d = 0; d < 256; d++) {
                float4 fv = *(const float4*)(featsT + d*SPAD + s0);
                float4 pv = *(const float4*)(p1 + d*64 + e0);
                acc[0][0] += fv.x*pv.x; acc[0][1] += fv.x*pv.y; acc[0][2] += fv.x*pv.z; acc[0][3] += fv.x*pv.w;
                acc[1][0] += fv.y*pv.x; acc[1][1] += fv.y*pv.y; acc[1][2] += fv.y*pv.z; acc[1][3] += fv.y*pv.w;
                acc[2][0] += fv.z*pv.x; acc[2][1] += fv.z*pv.y; acc[2][2] += fv.z*pv.z; acc[2][3] += fv.z*pv.w;
                acc[3][0] += fv.w*pv.x; acc[3][1] += fv.w*pv.y; acc[3][2] += fv.w*pv.z; acc[3][3] += fv.w*pv.w;
            }
            #pragma unroll
            for (int i = 0; i < 4; i++)
                #pragma unroll
                for (int j = 0; j < 4; j++)
                    f1[(s0+i)*64 + e0 + j] = acc[i][j];
        }
    }
    __syncthreads();

    // LN over 64 + relu per s, write transposed into f1T
    int warp = tid >> 5, lane = tid & 31;
    for (int s = warp; s < SS; s += 8) {
        float x0 = f1[s*64 + lane], x1 = f1[s*64 + 32 + lane];
        float sum = x0 + x1;
        #pragma unroll
        for (int o = 16; o; o >>= 1) sum += __shfl_xor_sync(0xffffffffu, sum, o);
        float m = sum * (1.f/64.f);
        float d0 = x0 - m, d1 = x1 - m;
        float vs = d0*d0 + d1*d1;
        #pragma unroll
        for (int o = 16; o; o >>= 1) vs += __shfl_xor_sync(0xffffffffu, vs, o);
        float inv = rsqrtf(vs*(1.f/64.f) + 1e-5f);
        f1T[lane*SPAD + s]        = fmaxf(d0*inv, 0.f);
        f1T[(32+lane)*SPAD + s]   = fmaxf(d1*inv, 0.f);
    }
    __syncthreads();

    // stage2: f2[s][d] = sum_e f1T[e][s] * p2[e][d]   (f2 reuses featsT region)
    float* f2 = featsT;
    {
        int td = tid & 63, tsg2 = tid >> 6;
        int d0 = td * 4;
        for (int sg = tsg2; sg < 13; sg += 4) {
            int s0 = sg * 4;
            float acc[4][4];
            #pragma unroll
            for (int i = 0; i < 4; i++)
                #pragma unroll
                for (int j = 0; j < 4; j++) acc[i][j] = 0.f;
            for (int e = 0; e < 64; e++) {
                float4 fv = *(const float4*)(f1T + e*SPAD + s0);
                float4 pv = *(const float4*)(p2 + e*256 + d0);
                acc[0][0] += fv.x*pv.x; acc[0][1] += fv.x*pv.y; acc[0][2] += fv.x*pv.z; acc[0][3] += fv.x*pv.w;
                acc[1][0] += fv.y*pv.x; acc[1][1] += fv.y*pv.y; acc[1][2] += fv.y*pv.z; acc[1][3] += fv.y*pv.w;
                acc[2][0] += fv.z*pv.x; acc[2][1] += fv.z*pv.y; acc[2][2] += fv.z*pv.z; acc[2][3] += fv.z*pv.w;
                acc[3][0] += fv.w*pv.x; acc[3][1] += fv.w*pv.y; acc[3][2] += fv.w*pv.z; acc[3][3] += fv.w*pv.w;
            }
            #pragma unroll
            for (int i = 0; i < 4; i++)
                #pragma unroll
                for (int j = 0; j < 4; j++)
                    f2[(s0+i)*256 + d0 + j] = acc[i][j];
        }
    }
    __syncthreads();

    // LN over 256 + relu, write out
    for (int s = warp; s < SS; s += 8) {
        float x[8]; float sum = 0.f;
        #pragma unroll
        for (int j = 0; j < 8; j++) { x[j] = f2[s*256 + j*32 + lane]; sum += x[j]; }
        #pragma unroll
        for (int o = 16; o; o >>= 1) sum += __shfl_xor_sync(0xffffffffu, sum, o);
        float m = sum * (1.f/256.f);
        float vs = 0.f;
        #pragma unroll
        for (int j = 0; j < 8; j++) { float dd = x[j]-m; vs += dd*dd; }
        #pragma unroll
        for (int o = 16; o; o >>= 1) vs += __shfl_xor_sync(0xffffffffu, vs, o);
        float inv = rsqrtf(vs*(1.f/256.f) + 1e-5f);
        #pragma unroll
        for (int j = 0; j < 8; j++)
            out[(size_t)n*12544 + s*256 + j*32 + lane] = fmaxf((x[j]-m)*inv, 0.f);
    }
}

// ---------------- host ----------------
extern "C" void kernel_launch(void* const* d_in, const int* in_sizes, int n_in,
                              void* d_out, int out_size) {
    const float* bboxes     = (const float*)d_in[0];
    const float* pf         = (const float*)d_in[1];
    const float* roi        = (const float*)d_in[2];
    const float* query      = (const float*)d_in[3];
    const float* cur        = (const float*)d_in[4];
    const float* w_qkv      = (const float*)d_in[5];
    const float* b_qkv      = (const float*)d_in[6];
    const float* w_attn_out = (const float*)d_in[7];
    const float* b_attn_out = (const float*)d_in[8];
    const float* w_dyn      = (const float*)d_in[9];
    const float* b_dyn      = (const float*)d_in[10];
    const float* w_dyn_out  = (const float*)d_in[11];
    const float* b_dyn_out  = (const float*)d_in[12];
    const float* w_ff1      = (const float*)d_in[13];
    const float* b_ff1      = (const float*)d_in[14];
    const float* w_ff2      = (const float*)d_in[15];
    const float* b_ff2      = (const float*)d_in[16];
    const float* w_cls      = (const float*)d_in[17];
    const float* w_logits   = (const float*)d_in[18];
    const float* b_logits   = (const float*)d_in[19];
    float* out = (float*)d_out;

    float *qk,*qp,*kp,*vp,*maskb,*ctx,*tgt2,*pf1,*params,*f2,*x,*pf3,*ffn,*t2,*fc,*clsy,*clsf;
    cudaGetSymbolAddress((void**)&qk,    g_qk);
    cudaGetSymbolAddress((void**)&qp,    g_qp);
    cudaGetSymbolAddress((void**)&kp,    g_kp);
    cudaGetSymbolAddress((void**)&vp,    g_vp);
    cudaGetSymbolAddress((void**)&maskb, g_mask);
    cudaGetSymbolAddress((void**)&ctx,   g_ctx);
    cudaGetSymbolAddress((void**)&tgt2,  g_tgt2);
    cudaGetSymbolAddress((void**)&pf1,   g_pf1);
    cudaGetSymbolAddress((void**)&params,g_params);
    cudaGetSymbolAddress((void**)&f2,    g_f2);
    cudaGetSymbolAddress((void**)&x,     g_x);
    cudaGetSymbolAddress((void**)&pf3,   g_pf3);
    cudaGetSymbolAddress((void**)&ffn,   g_ffn);
    cudaGetSymbolAddress((void**)&t2,    g_t2);
    cudaGetSymbolAddress((void**)&fc,    g_fc);
    cudaGetSymbolAddress((void**)&clsy,  g_clsy);
    cudaGetSymbolAddress((void**)&clsf,  g_clsf);

    const int GEMM_SMEM = 4 * GTILE * 4;   // 73728 B
    cudaFuncSetAttribute(tf32_gemm, cudaFuncAttributeMaxDynamicSharedMemorySize, GEMM_SMEM);
    cudaFuncSetAttribute(dynconv_kernel, cudaFuncAttributeMaxDynamicSharedMemorySize, DYN_SMEM);

    auto grd = [](int M, int N) { return dim3((unsigned)((N+127)/128), (unsigned)((M+127)/128)); };

    // 1. IoU-relation mask
    mask_kernel<<<dim3(NRr, NB), 320>>>(bboxes, cur, maskb);
    // 2. qk = pf + query
    add_kernel<<<(ROWS*DD_+255)/256, 256>>>(pf, query, qk, ROWS*DD_);
    // 3. QKV projections
    tf32_gemm<<<grd(ROWS,256), 256, GEMM_SMEM>>>(qk, w_qkv,           b_qkv,     qp, ROWS, 256, 256, 0);
    tf32_gemm<<<grd(ROWS,256), 256, GEMM_SMEM>>>(qk, w_qkv + 256*256, b_qkv+256, kp, ROWS, 256, 256, 0);
    tf32_gemm<<<grd(ROWS,256), 256, GEMM_SMEM>>>(pf, w_qkv + 512*256, b_qkv+512, vp, ROWS, 256, 256, 0);
    // 4. masked MHSA
    attn_kernel<<<NB*HH*3, 128>>>(qp, kp, vp, maskb, ctx);
    // 5. out proj + norm1*mask
    tf32_gemm<<<grd(ROWS,256), 256, GEMM_SMEM>>>(ctx, w_attn_out, b_attn_out, tgt2, ROWS, 256, 256, 0);
    ln_res_mask_kernel<<<ROWS, 256>>>(pf, tgt2, cur, pf1);
    // 6. DynamicConv params GEMM (dominant)
    tf32_gemm<<<grd(ROWS,32768), 256, GEMM_SMEM>>>(pf1, w_dyn, b_dyn, params, ROWS, 32768, 256, 0);
    // 7. per-instance dynamic conv
    dynconv_kernel<<<ROWS, 256, DYN_SMEM>>>(roi, params, f2);
    // 8. dyn out proj + norm2
    tf32_gemm<<<grd(ROWS,256), 256, GEMM_SMEM>>>(f2, w_dyn_out, b_dyn_out, x, ROWS, 256, 12544, 0);
    post_dyn_kernel<<<ROWS, 256>>>(x, pf1, pf3);
    // 9. FFN + norm3 (with cls mask fused)
    tf32_gemm<<<grd(ROWS,2048), 256, GEMM_SMEM>>>(pf3, w_ff1, b_ff1, ffn, ROWS, 2048, 256, 1);
    tf32_gemm<<<grd(ROWS,256),  256, GEMM_SMEM>>>(ffn, w_ff2, b_ff2, t2, ROWS, 256, 2048, 0);
    ln_res_mask_kernel<<<ROWS, 256>>>(pf3, t2, cur, fc);
    // 10. cls tower + logits
    tf32_gemm<<<grd(ROWS,256), 256, GEMM_SMEM>>>(fc, w_cls, nullptr, clsy, ROWS, 256, 256, 0);
    ln_relu_kernel<<<ROWS, 256>>>(clsy, clsf);
    tf32_gemm<<<grd(ROWS,80), 256, GEMM_SMEM>>>(clsf, w_logits, b_logits, out, ROWS, 80, 256, 0);
}